// round 2
// baseline (speedup 1.0000x reference)
#include <cuda_runtime.h>
#include <math.h>

#define NATOMS 16384
#define MCL    4096
#define BG     64
#define KCL    64
#define HID    256
#define FIL    256
#define ECH    64
#define LINT   6
#define TROWS  2048
#define TDELTA 0.005f
#define INV_TDELTA 200.0f
#define LN2F   0.69314718055994530942f
#define CUTOFF 10.0f

// -------- scratch (static device arrays; no cudaMalloc anywhere) --------
__device__ float g_pos4[MCL * 4];          // cluster positions (xyz + pad)
__device__ float g_cnt[MCL];               // atoms per cluster
__device__ float g_G[TROWS * ECH];         // gaussian smearing on table grid
__device__ float g_Cenv[TROWS];            // cutoff envelope on table grid
__device__ float g_hidden[TROWS * FIL];    // table-build intermediate
__device__ float g_table[TROWS * FIL];     // W(d)*C(d), current layer
__device__ float g_tp[TROWS * FIL * 2];    // packed (T[i],T[i+1]) pairs
__device__ float g_x[MCL * FIL];           // x = h @ lin1 (reused for x2)
__device__ float g_agg[MCL * FIL];         // edge aggregation

// shifted softplus, stable
__device__ __forceinline__ float sspf(float x) {
    float ax = fabsf(x);
    return fmaxf(x, 0.f) + log1pf(expf(-ax)) - LN2F;
}

// runtime detection: subgraph_index int64 vs int32
__device__ __forceinline__ bool sg_is64(const void* sg) {
    unsigned long long probe = ((const unsigned long long*)sg)[NATOMS / 2 - 1];
    return probe < (unsigned long long)MCL;
}
__device__ __forceinline__ int sg_at(const void* sg, int a, bool is64) {
    return is64 ? (int)((const long long*)sg)[a] : ((const int*)sg)[a];
}

// -------- init / coarse grain --------
__global__ void __launch_bounds__(256) zero_k(float* __restrict__ hout) {
    int i = blockIdx.x * 256 + threadIdx.x;
    if (i < MCL * HID) hout[i] = 0.f;
    if (i < MCL * 4)   g_pos4[i] = 0.f;
    if (i < MCL)       g_cnt[i] = 0.f;
}

__global__ void __launch_bounds__(256) scatter_pos_k(const float* __restrict__ pos,
                                                     const void* __restrict__ sg) {
    int a = blockIdx.x * 256 + threadIdx.x;
    if (a >= NATOMS) return;
    bool is64 = sg_is64(sg);
    int c = sg_at(sg, a, is64);
    atomicAdd(&g_pos4[c * 4 + 0], pos[a * 3 + 0]);
    atomicAdd(&g_pos4[c * 4 + 1], pos[a * 3 + 1]);
    atomicAdd(&g_pos4[c * 4 + 2], pos[a * 3 + 2]);
    atomicAdd(&g_cnt[c], 1.f);
}

__global__ void __launch_bounds__(256) scatter_attr_k(const float* __restrict__ attr,
                                                      const void* __restrict__ sg,
                                                      float* __restrict__ hout) {
    int a = blockIdx.x;       // atom
    int f = threadIdx.x;      // feature
    bool is64 = sg_is64(sg);
    int c = sg_at(sg, a, is64);
    atomicAdd(&hout[c * HID + f], attr[a * HID + f]);
}

__global__ void __launch_bounds__(256) norm_attr_k(float* __restrict__ hout) {
    int i = blockIdx.x * 256 + threadIdx.x;  // M*HID
    int c = i >> 8;
    float n = fmaxf(g_cnt[c], 1.f);
    hout[i] = hout[i] / n;
}

__global__ void __launch_bounds__(256) norm_pos_k() {
    int c = blockIdx.x * 256 + threadIdx.x;
    if (c >= MCL) return;
    float n = fmaxf(g_cnt[c], 1.f);
    g_pos4[c * 4 + 0] /= n;
    g_pos4[c * 4 + 1] /= n;
    g_pos4[c * 4 + 2] /= n;
}

// -------- table-grid gaussians + cutoff envelope --------
__global__ void __launch_bounds__(256) gauss_k() {
    const float spacing = CUTOFF / 63.0f;
    const float coeff = -0.5f / (spacing * spacing);
    int t = blockIdx.x * 256 + threadIdx.x;
    if (t < TROWS * ECH) {
        int row = t >> 6, k = t & 63;
        float d = row * TDELTA;
        float u = d - (float)k * spacing;
        g_G[t] = expf(coeff * u * u);
    }
    if (t < TROWS) {
        float d = t * TDELTA;
        float c = (d <= CUTOFF) ? 0.5f * (cospif(d * (1.0f / CUTOFF)) + 1.0f) : 0.f;
        g_Cenv[t] = c;
    }
}

// -------- fp32 SGEMM with fused epilogue --------
// C[M,N] = A[M,K] @ B[K,N]; ops: +bias, ssp, *rowscale, +resid
#define OP_BIAS 1
#define OP_SSP  2
#define OP_ROWS 4
#define OP_RES  8

__global__ void __launch_bounds__(256) sgemm_k(const float* __restrict__ A,
                                               const float* __restrict__ B,
                                               const float* __restrict__ bias,
                                               const float* __restrict__ rowscale,
                                               const float* __restrict__ resid,
                                               float* __restrict__ C,
                                               int M, int N, int K, int ops) {
    __shared__ float As[16][68];   // [k][m], padded
    __shared__ float Bs[16][64];   // [k][n]
    int tid = threadIdx.x;
    int tx = tid & 15, ty = tid >> 4;
    int bm = blockIdx.y, bn = blockIdx.x;
    const float* Ab = A + (size_t)bm * 64 * K;
    const float* Bb = B + bn * 64;

    float acc[4][4];
#pragma unroll
    for (int i = 0; i < 4; i++)
#pragma unroll
        for (int j = 0; j < 4; j++) acc[i][j] = 0.f;

    int la_r = tid >> 4;   // 0..15 (m base)
    int la_c = tid & 15;   // 0..15 (k)
    int lb_r = tid >> 6;   // 0..3
    int lb_c = tid & 63;   // 0..63

    for (int k0 = 0; k0 < K; k0 += 16) {
#pragma unroll
        for (int q = 0; q < 4; q++)
            As[la_c][la_r + 16 * q] = Ab[(size_t)(la_r + 16 * q) * K + k0 + la_c];
#pragma unroll
        for (int q = 0; q < 4; q++)
            Bs[lb_r + 4 * q][lb_c] = Bb[(size_t)(k0 + lb_r + 4 * q) * N + lb_c];
        __syncthreads();
#pragma unroll
        for (int kk = 0; kk < 16; kk++) {
            float4 a4 = *(const float4*)&As[kk][ty * 4];
            float4 b4 = *(const float4*)&Bs[kk][tx * 4];
            float av[4] = {a4.x, a4.y, a4.z, a4.w};
            float bv[4] = {b4.x, b4.y, b4.z, b4.w};
#pragma unroll
            for (int i = 0; i < 4; i++)
#pragma unroll
                for (int j = 0; j < 4; j++)
                    acc[i][j] = fmaf(av[i], bv[j], acc[i][j]);
        }
        __syncthreads();
    }

    int row0 = bm * 64 + ty * 4;
    int col0 = bn * 64 + tx * 4;
#pragma unroll
    for (int i = 0; i < 4; i++) {
        int row = row0 + i;
        float rs = (ops & OP_ROWS) ? rowscale[row] : 1.f;
#pragma unroll
        for (int j = 0; j < 4; j++) {
            float v = acc[i][j];
            int col = col0 + j;
            if (ops & OP_BIAS) v += bias[col];
            if (ops & OP_SSP)  v = sspf(v);
            if (ops & OP_ROWS) v *= rs;
            size_t o = (size_t)row * N + col;
            if (ops & OP_RES)  v += resid[o];
            C[o] = v;
        }
    }
}

// -------- pack table rows into (T[i],T[i+1]) pairs --------
__global__ void __launch_bounds__(256) pack_k() {
    int t = blockIdx.x * 256 + threadIdx.x;
    if (t >= TROWS * FIL) return;
    int f = t & 255;
    int row = t >> 8;
    float a = g_table[t];
    int row2 = min(row + 1, TROWS - 1);
    float b = g_table[row2 * FIL + f];
    ((float2*)g_tp)[t] = make_float2(a, b);
}

// -------- fused edge kernel: lerp W(d), gather x[src], reduce per dest --------
// grid: (4 dest-blocks of 16, 64 graphs), 256 threads (thread = feature)
__global__ void __launch_bounds__(256) agg_k(const float* __restrict__ x,
                                             float* __restrict__ agg) {
    extern __shared__ float sm[];
    float* sx   = sm;                                   // 64*256
    float* spos = sm + KCL * HID;                       // 64*4
    int*   sidx = (int*)(sm + KCL * HID + KCL * 4);     // 16*63
    float* st   = sm + KCL * HID + KCL * 4 + 16 * 63;   // 16*63

    int g  = blockIdx.y;
    int jb = blockIdx.x;
    int tid = threadIdx.x;

    const float* xg = x + (size_t)g * KCL * HID;
    for (int k = tid; k < KCL * HID; k += 256) sx[k] = xg[k];
    if (tid < KCL * 4) spos[tid] = g_pos4[g * KCL * 4 + tid];
    __syncthreads();

    // precompute per-edge table index + frac for this CTA's 16 dests
    for (int e = tid; e < 16 * 63; e += 256) {
        int j = jb * 16 + e / 63;        // local dest
        int ii = e % 63;
        int i = ii + (ii >= j);          // local src, skip self
        float dx = spos[j * 4 + 0] - spos[i * 4 + 0];
        float dy = spos[j * 4 + 1] - spos[i * 4 + 1];
        float dz = spos[j * 4 + 2] - spos[i * 4 + 2];
        float d = sqrtf(dx * dx + dy * dy + dz * dz);
        float u = d * INV_TDELTA;
        int idx = (int)u;
        if (idx > TROWS - 2) idx = TROWS - 2;   // rows >= d=10 are exactly 0
        sidx[e] = idx;
        st[e] = u - (float)idx;
    }
    __syncthreads();

    int f = tid;
    const float2* T2 = (const float2*)g_tp;

#pragma unroll 1
    for (int jj = 0; jj < 16; jj++) {
        int j = jb * 16 + jj;
        int ebase = jj * 63;
        float acc = 0.f;
#pragma unroll 3
        for (int ii = 0; ii < 63; ii++) {
            int e = ebase + ii;
            int i = ii + (ii >= j);
            int idx = sidx[e];
            float t = st[e];
            float2 p = T2[(size_t)idx * FIL + f];
            float w = p.x + t * (p.y - p.x);
            acc = fmaf(sx[i * HID + f], w, acc);
        }
        agg[((size_t)g * KCL + j) * FIL + f] = acc;
    }
}

extern "C" void kernel_launch(void* const* d_in, const int* in_sizes, int n_in,
                              void* d_out, int out_size) {
    const float* pos  = (const float*)d_in[0];
    const float* attr = (const float*)d_in[1];
    const void*  sg   = d_in[2];
    // params are always the LAST 9 inputs (scalar-count agnostic)
    const float* mlp_w1 = (const float*)d_in[n_in - 9];
    const float* mlp_b1 = (const float*)d_in[n_in - 8];
    const float* mlp_w2 = (const float*)d_in[n_in - 7];
    const float* mlp_b2 = (const float*)d_in[n_in - 6];
    const float* lin1_w = (const float*)d_in[n_in - 5];
    const float* lin2_w = (const float*)d_in[n_in - 4];
    const float* lin2_b = (const float*)d_in[n_in - 3];
    const float* lin_w  = (const float*)d_in[n_in - 2];
    const float* lin_b  = (const float*)d_in[n_in - 1];
    float* h = (float*)d_out;

    float *pG, *pCenv, *pHidden, *pTable, *pX, *pAgg;
    cudaGetSymbolAddress((void**)&pG, g_G);
    cudaGetSymbolAddress((void**)&pCenv, g_Cenv);
    cudaGetSymbolAddress((void**)&pHidden, g_hidden);
    cudaGetSymbolAddress((void**)&pTable, g_table);
    cudaGetSymbolAddress((void**)&pX, g_x);
    cudaGetSymbolAddress((void**)&pAgg, g_agg);

    const int smem_agg = KCL * HID * 4 + KCL * 4 * 4 + 16 * 63 * 4 * 2; // 74624 B
    cudaFuncSetAttribute(agg_k, cudaFuncAttributeMaxDynamicSharedMemorySize, smem_agg);

    // coarse grain
    zero_k<<<(MCL * HID + 255) / 256, 256>>>(h);
    scatter_pos_k<<<(NATOMS + 255) / 256, 256>>>(pos, sg);
    scatter_attr_k<<<NATOMS, 256>>>(attr, sg, h);
    norm_attr_k<<<(MCL * HID + 255) / 256, 256>>>(h);
    norm_pos_k<<<(MCL + 255) / 256, 256>>>();
    gauss_k<<<(TROWS * ECH + 255) / 256, 256>>>();

    dim3 gT(FIL / 64, TROWS / 64);   // table-build GEMMs
    dim3 gM(FIL / 64, MCL / 64);     // cluster GEMMs

    for (int l = 0; l < LINT; l++) {
        // hidden = ssp(G @ w1[l] + b1[l])       (TROWS x FIL, K=ECH)
        sgemm_k<<<gT, 256>>>(pG, mlp_w1 + (size_t)l * ECH * FIL,
                             mlp_b1 + (size_t)l * FIL, nullptr, nullptr,
                             pHidden, TROWS, FIL, ECH, OP_BIAS | OP_SSP);
        // table = (hidden @ w2[l] + b2[l]) * Cenv[row]
        sgemm_k<<<gT, 256>>>(pHidden, mlp_w2 + (size_t)l * FIL * FIL,
                             mlp_b2 + (size_t)l * FIL, pCenv, nullptr,
                             pTable, TROWS, FIL, FIL, OP_BIAS | OP_ROWS);
        pack_k<<<(TROWS * FIL + 255) / 256, 256>>>();

        // x = h @ lin1_w[l]                     (M x FIL, K=HID)
        sgemm_k<<<gM, 256>>>(h, lin1_w + (size_t)l * HID * FIL,
                             nullptr, nullptr, nullptr,
                             pX, MCL, FIL, HID, 0);
        // agg = segment_sum(x[src] * W, dest)
        agg_k<<<dim3(4, BG), 256, smem_agg>>>(pX, pAgg);
        // x2 = ssp(agg @ lin2_w[l] + lin2_b[l])
        sgemm_k<<<gM, 256>>>(pAgg, lin2_w + (size_t)l * FIL * HID,
                             lin2_b + (size_t)l * HID, nullptr, nullptr,
                             pX, MCL, HID, FIL, OP_BIAS | OP_SSP);
        // h = h + (x2 @ lin_w[l] + lin_b[l])
        sgemm_k<<<gM, 256>>>(pX, lin_w + (size_t)l * HID * HID,
                             lin_b + (size_t)l * HID, nullptr, h,
                             h, MCL, HID, HID, OP_BIAS | OP_RES);
    }
}

// round 6
// speedup vs baseline: 1.3075x; 1.3075x over previous
#include <cuda_runtime.h>
#include <cuda_bf16.h>
#include <cuda_fp16.h>
#include <math.h>
#include <stdint.h>

#define NATOMS 16384
#define MCL    4096
#define BG     64
#define KCL    64
#define HID    256
#define FIL    256
#define ECH    64
#define LINT   6
#define TROWS  2048
#define TDELTA 0.005f
#define INV_TDELTA 200.0f
#define LN2F   0.69314718055994530942f
#define CUTOFF 10.0f

// -------- scratch (static device arrays; no cudaMalloc anywhere) --------
__device__ float g_pos4[MCL * 4];
__device__ float g_G[TROWS * ECH];
__device__ float g_Cenv[TROWS];
__device__ float g_hidden[LINT * TROWS * FIL];
__device__ float g_table[LINT * TROWS * FIL];
__device__ __half2 g_tph[LINT * TROWS * FIL];
__device__ float g_x[MCL * FIL];
__device__ float g_agg[MCL * FIL];

// transposed + hi/lo split weights (bf16), [L][N][K]
__device__ __nv_bfloat16 g_w1T_hi[LINT * FIL * ECH];
__device__ __nv_bfloat16 g_w1T_lo[LINT * FIL * ECH];
__device__ __nv_bfloat16 g_w2T_hi[LINT * FIL * FIL];
__device__ __nv_bfloat16 g_w2T_lo[LINT * FIL * FIL];
__device__ __nv_bfloat16 g_l1T_hi[LINT * HID * FIL];
__device__ __nv_bfloat16 g_l1T_lo[LINT * HID * FIL];
__device__ __nv_bfloat16 g_l2T_hi[LINT * FIL * HID];
__device__ __nv_bfloat16 g_l2T_lo[LINT * FIL * HID];
__device__ __nv_bfloat16 g_lT_hi[LINT * HID * HID];
__device__ __nv_bfloat16 g_lT_lo[LINT * HID * HID];

// ---------------- helpers ----------------
__device__ __forceinline__ uint32_t smem_u32(const void* p) {
    uint32_t a;
    asm("{ .reg .u64 t; cvta.to.shared.u64 t, %1; cvt.u32.u64 %0, t; }" : "=r"(a) : "l"(p));
    return a;
}
__device__ __forceinline__ float sspf(float x) {
    float ax = fabsf(x);
    return fmaxf(x, 0.f) + log1pf(expf(-ax)) - LN2F;
}
__device__ __forceinline__ bool sg_is64(const void* sg) {
    unsigned long long probe = ((const unsigned long long*)sg)[NATOMS / 2 - 1];
    return probe < (unsigned long long)MCL;
}
__device__ __forceinline__ int sg_at(const void* sg, int a, bool is64) {
    return is64 ? (int)((const long long*)sg)[a] : ((const int*)sg)[a];
}
__device__ __forceinline__ int lbound(const void* sg, bool is64, int val) {
    int lo = 0, hi = NATOMS;
    while (lo < hi) {
        int mid = (lo + hi) >> 1;
        if (sg_at(sg, mid, is64) < val) lo = mid + 1; else hi = mid;
    }
    return lo;
}
__device__ __forceinline__ uint32_t pack_bf2(__nv_bfloat16 a, __nv_bfloat16 b) {
    return ((uint32_t)__bfloat16_as_ushort(b) << 16) | (uint32_t)__bfloat16_as_ushort(a);
}

#define CP16(dst, src) \
    asm volatile("cp.async.cg.shared.global [%0], [%1], 16;" :: "r"(dst), "l"(src) : "memory")
#define CP_COMMIT() asm volatile("cp.async.commit_group;" ::: "memory")
#define CP_WAIT0()  asm volatile("cp.async.wait_group 0;" ::: "memory")
#define LDSM4(r, addr) \
    asm volatile("ldmatrix.sync.aligned.m8n8.x4.shared.b16 {%0,%1,%2,%3}, [%4];" \
        : "=r"((r)[0]), "=r"((r)[1]), "=r"((r)[2]), "=r"((r)[3]) : "r"(addr))
#define MMA_BF16(c, a, b0, b1) \
    asm volatile("mma.sync.aligned.m16n8k16.row.col.f32.bf16.bf16.f32 " \
        "{%0,%1,%2,%3}, {%4,%5,%6,%7}, {%8,%9}, {%0,%1,%2,%3};" \
        : "+f"((c)[0]), "+f"((c)[1]), "+f"((c)[2]), "+f"((c)[3]) \
        : "r"((a)[0]), "r"((a)[1]), "r"((a)[2]), "r"((a)[3]), "r"(b0), "r"(b1))

// ---------------- coarse grain: gather over contiguous sorted ranges ----------------
__global__ void __launch_bounds__(256) cg_k(const float* __restrict__ pos,
                                            const float* __restrict__ attr,
                                            const void* __restrict__ sg,
                                            float* __restrict__ h) {
    __shared__ int s_lo, s_hi;
    int c = blockIdx.x, f = threadIdx.x;
    bool is64 = sg_is64(sg);
    if (f == 0) s_lo = lbound(sg, is64, c);
    if (f == 1) s_hi = lbound(sg, is64, c + 1);
    __syncthreads();
    int lo = s_lo, hi = s_hi;
    float inv = 1.f / fmaxf((float)(hi - lo), 1.f);
    float s = 0.f;
    for (int a = lo; a < hi; a++) s += attr[(size_t)a * HID + f];
    h[(size_t)c * HID + f] = s * inv;
    if (f < 3) {
        float p = 0.f;
        for (int a = lo; a < hi; a++) p += pos[a * 3 + f];
        g_pos4[c * 4 + f] = p * inv;
    }
    if (f == 3) g_pos4[c * 4 + 3] = 0.f;
}

// ---------------- table-grid gaussians + cutoff envelope ----------------
__global__ void __launch_bounds__(256) gauss_k() {
    const float spacing = CUTOFF / 63.0f;
    const float coeff = -0.5f / (spacing * spacing);
    int t = blockIdx.x * 256 + threadIdx.x;
    if (t < TROWS * ECH) {
        int row = t >> 6, k = t & 63;
        float d = row * TDELTA;
        float u = d - (float)k * spacing;
        g_G[t] = expf(coeff * u * u);
    }
    if (t < TROWS) {
        float d = t * TDELTA;
        float c = (d <= CUTOFF) ? 0.5f * (cospif(d * (1.0f / CUTOFF)) + 1.0f) : 0.f;
        g_Cenv[t] = c;
    }
}

// transpose + hi/lo split: in [L][R][C] fp32 -> out [L][C][R] bf16 hi/lo
__global__ void __launch_bounds__(256) tsplit_k(const float* __restrict__ in,
                                                __nv_bfloat16* __restrict__ hi,
                                                __nv_bfloat16* __restrict__ lo,
                                                int R, int C) {
    int l = blockIdx.y;
    int i = blockIdx.x * 256 + threadIdx.x;
    if (i >= R * C) return;
    int r = i / C, c = i % C;
    float v = in[(size_t)l * R * C + i];
    __nv_bfloat16 h = __float2bfloat16(v);
    float vl = v - __bfloat162float(h);
    size_t o = (size_t)l * R * C + (size_t)c * R + r;
    hi[o] = h;
    lo[o] = __float2bfloat16(vl);
}

// pack table rows into (T[i],T[i+1]) half2 pairs (all layers)
__global__ void __launch_bounds__(256) pack_k() {
    int t = blockIdx.x * 256 + threadIdx.x;
    if (t >= LINT * TROWS * FIL) return;
    int f = t & 255;
    int rest = t >> 8;                 // l*2048 + row
    int row = rest & (TROWS - 1);
    int l = rest >> 11;
    float a = g_table[t];
    int row2 = min(row + 1, TROWS - 1);
    float b = g_table[((size_t)l * TROWS + row2) * FIL + f];
    g_tph[t] = __floats2half2_rn(a, b);
}

// ---------------- HMMA bf16 split-precision GEMM ----------------
// C[M,N] = A[M,K] @ B[K,N]; A fp32 row-major; B pre-transposed+split bf16 [N][K].
// CTA tile 128x64, warp tile 32x32, KC=32 double-buffered.
#define OP_BIAS 1
#define OP_SSP  2
#define OP_ROWS 4
#define OP_RES  8

#define ASTR   80                       // smem row stride (bytes): 32 bf16 + 16B pad
#define A_BY   (128 * ASTR)             // 10240
#define B_BY   (64 * ASTR)              // 5120
#define OFF_AL A_BY
#define OFF_BH (2 * A_BY)
#define OFF_BL (2 * A_BY + B_BY)
#define GBUF   (2 * A_BY + 2 * B_BY)    // 30720

__device__ __forceinline__ void sts_a_split(char* buf, const float4* pref, int arow, int ahalf) {
    char* dh = buf + arow * ASTR + ahalf * 32;
#pragma unroll
    for (int q = 0; q < 4; q++) {
        float4 v = pref[q];
        __nv_bfloat16 h0 = __float2bfloat16(v.x), h1 = __float2bfloat16(v.y);
        __nv_bfloat16 h2 = __float2bfloat16(v.z), h3 = __float2bfloat16(v.w);
        __nv_bfloat16 l0 = __float2bfloat16(v.x - __bfloat162float(h0));
        __nv_bfloat16 l1 = __float2bfloat16(v.y - __bfloat162float(h1));
        __nv_bfloat16 l2 = __float2bfloat16(v.z - __bfloat162float(h2));
        __nv_bfloat16 l3 = __float2bfloat16(v.w - __bfloat162float(h3));
        *(uint2*)(dh + q * 8)          = make_uint2(pack_bf2(h0, h1), pack_bf2(h2, h3));
        *(uint2*)(dh + OFF_AL + q * 8) = make_uint2(pack_bf2(l0, l1), pack_bf2(l2, l3));
    }
}

__global__ void __launch_bounds__(256, 1)
gemm_k(const float* __restrict__ A,
       const __nv_bfloat16* __restrict__ Bhi, const __nv_bfloat16* __restrict__ Blo,
       const float* __restrict__ bias, const float* __restrict__ rowscale,
       const float* __restrict__ resid, float* __restrict__ C,
       int N, int K, int ops,
       size_t zA, size_t zB, size_t zBias, size_t zC) {
    extern __shared__ __align__(16) char sm[];
    int z = blockIdx.z;
    A += (size_t)z * zA; Bhi += (size_t)z * zB; Blo += (size_t)z * zB;
    C += (size_t)z * zC;
    const float* biasz = bias ? bias + (size_t)z * zBias : (const float*)0;

    int tid = threadIdx.x;
    int lane = tid & 31, wid = tid >> 5;
    int wm = wid >> 1, wn = wid & 1;
    int bm = blockIdx.y, bn = blockIdx.x;
    uint32_t smu = smem_u32(sm);

    // staging coords
    int arow = tid >> 1, ahalf = tid & 1;
    const float* aptr = A + (size_t)(bm * 128 + arow) * K + ahalf * 16;
    int brow = tid >> 2, bseg = tid & 3;
    const __nv_bfloat16* bhp = Bhi + (size_t)(bn * 64 + brow) * K + bseg * 8;
    const __nv_bfloat16* blp = Blo + (size_t)(bn * 64 + brow) * K + bseg * 8;
    uint32_t bdst = brow * ASTR + bseg * 16;

    float acc[2][4][4];
#pragma unroll
    for (int i = 0; i < 2; i++)
#pragma unroll
        for (int j = 0; j < 4; j++)
#pragma unroll
            for (int q = 0; q < 4; q++) acc[i][j][q] = 0.f;

    int NC = K >> 5;
    float4 pref[4];

    // prologue: stage chunk 0 into buffer 0
    {
        pref[0] = *(const float4*)(aptr + 0);
        pref[1] = *(const float4*)(aptr + 4);
        pref[2] = *(const float4*)(aptr + 8);
        pref[3] = *(const float4*)(aptr + 12);
        CP16(smu + OFF_BH + bdst, bhp);
        CP16(smu + OFF_BL + bdst, blp);
        CP_COMMIT();
        sts_a_split(sm, pref, arow, ahalf);
        CP_WAIT0();
        __syncthreads();
    }

    for (int c = 0; c < NC; c++) {
        uint32_t cur = smu + (c & 1) * GBUF;
        char* nxtp = sm + ((c + 1) & 1) * GBUF;
        uint32_t nxtu = smu + ((c + 1) & 1) * GBUF;
        if (c + 1 < NC) {
            int kc = (c + 1) * 32;
            const float* p = aptr + kc;
            pref[0] = *(const float4*)(p + 0);
            pref[1] = *(const float4*)(p + 4);
            pref[2] = *(const float4*)(p + 8);
            pref[3] = *(const float4*)(p + 12);
            CP16(nxtu + OFF_BH + bdst, bhp + kc);
            CP16(nxtu + OFF_BL + bdst, blp + kc);
            CP_COMMIT();
        }
        // ---- compute from cur ----
#pragma unroll
        for (int ks = 0; ks < 2; ks++) {
            uint32_t ah[2][4], al[2][4];
#pragma unroll
            for (int mt = 0; mt < 2; mt++) {
                uint32_t addr = cur + (wm * 32 + mt * 16 + (lane & 15)) * ASTR
                              + ks * 32 + (lane >> 4) * 16;
                LDSM4(ah[mt], addr);
                LDSM4(al[mt], addr + OFF_AL);
            }
            uint32_t bh[2][4], bl[2][4];
#pragma unroll
            for (int pr = 0; pr < 2; pr++) {
                uint32_t addr = cur + OFF_BH + (wn * 32 + pr * 16 + (lane & 15)) * ASTR
                              + ks * 32 + (lane >> 4) * 16;
                LDSM4(bh[pr], addr);
                LDSM4(bl[pr], addr + B_BY);
            }
#pragma unroll
            for (int mt = 0; mt < 2; mt++)
#pragma unroll
                for (int nt = 0; nt < 4; nt++) {
                    float* cc = acc[mt][nt];
                    uint32_t bh0 = bh[nt >> 1][nt & 1], bh1 = bh[nt >> 1][2 + (nt & 1)];
                    uint32_t bl0 = bl[nt >> 1][nt & 1], bl1 = bl[nt >> 1][2 + (nt & 1)];
                    MMA_BF16(cc, ah[mt], bh0, bh1);
                    MMA_BF16(cc, ah[mt], bl0, bl1);
                    MMA_BF16(cc, al[mt], bh0, bh1);
                }
        }
        if (c + 1 < NC) {
            CP_WAIT0();
            sts_a_split(nxtp, pref, arow, ahalf);
        }
        __syncthreads();
    }

    // ---- epilogue ----
    int lr = lane >> 2, lc = (lane & 3) * 2;
#pragma unroll
    for (int mt = 0; mt < 2; mt++) {
#pragma unroll
        for (int half = 0; half < 2; half++) {
            int row = bm * 128 + wm * 32 + mt * 16 + half * 8 + lr;
            float rs = (ops & OP_ROWS) ? rowscale[row] : 1.f;
#pragma unroll
            for (int nt = 0; nt < 4; nt++) {
                int col = bn * 64 + wn * 32 + nt * 8 + lc;
                float v0 = acc[mt][nt][half * 2 + 0];
                float v1 = acc[mt][nt][half * 2 + 1];
                if (ops & OP_BIAS) {
                    float2 b = *(const float2*)(biasz + col);
                    v0 += b.x; v1 += b.y;
                }
                if (ops & OP_SSP) { v0 = sspf(v0); v1 = sspf(v1); }
                if (ops & OP_ROWS) { v0 *= rs; v1 *= rs; }
                size_t o = (size_t)row * N + col;
                if (ops & OP_RES) {
                    float2 r = *(const float2*)(resid + o);
                    v0 += r.x; v1 += r.y;
                }
                *(float2*)(C + o) = make_float2(v0, v1);
            }
        }
    }
}

// ---------------- fused edge aggregation (half2 table lerp) ----------------
__global__ void __launch_bounds__(256) agg_k(const float* __restrict__ x,
                                             const __half2* __restrict__ T2,
                                             float* __restrict__ agg) {
    extern __shared__ float smf[];
    float* sx   = smf;                                   // 64*256
    float* spos = smf + KCL * HID;                       // 64*4
    int*   sidx = (int*)(smf + KCL * HID + KCL * 4);     // 16*63
    float* st   = smf + KCL * HID + KCL * 4 + 16 * 63;   // 16*63

    int g  = blockIdx.y;
    int jb = blockIdx.x;
    int tid = threadIdx.x;

    const float* xg = x + (size_t)g * KCL * HID;
    for (int k = tid; k < KCL * HID; k += 256) sx[k] = xg[k];
    if (tid < KCL * 4) spos[tid] = g_pos4[g * KCL * 4 + tid];
    __syncthreads();

    for (int e = tid; e < 16 * 63; e += 256) {
        int j = jb * 16 + e / 63;
        int ii = e % 63;
        int i = ii + (ii >= j);
        float dx = spos[j * 4 + 0] - spos[i * 4 + 0];
        float dy = spos[j * 4 + 1] - spos[i * 4 + 1];
        float dz = spos[j * 4 + 2] - spos[i * 4 + 2];
        float d = sqrtf(dx * dx + dy * dy + dz * dz);
        float u = d * INV_TDELTA;
        int idx = (int)u;
        if (idx > TROWS - 2) idx = TROWS - 2;
        sidx[e] = idx;
        st[e] = u - (float)idx;
    }
    __syncthreads();

    int f = tid;
#pragma unroll 1
    for (int jj = 0; jj < 16; jj++) {
        int j = jb * 16 + jj;
        int ebase = jj * 63;
        float acc = 0.f;
#pragma unroll 3
        for (int ii = 0; ii < 63; ii++) {
            int e = ebase + ii;
            int i = ii + (ii >= j);
            float2 p = __half22float2(T2[(size_t)sidx[e] * FIL + f]);
            float w = p.x + st[e] * (p.y - p.x);
            acc = fmaf(sx[i * HID + f], w, acc);
        }
        agg[((size_t)g * KCL + j) * FIL + f] = acc;
    }
}

extern "C" void kernel_launch(void* const* d_in, const int* in_sizes, int n_in,
                              void* d_out, int out_size) {
    const float* pos  = (const float*)d_in[0];
    const float* attr = (const float*)d_in[1];
    const void*  sg   = d_in[2];
    const float* mlp_w1 = (const float*)d_in[n_in - 9];
    const float* mlp_b1 = (const float*)d_in[n_in - 8];
    const float* mlp_w2 = (const float*)d_in[n_in - 7];
    const float* mlp_b2 = (const float*)d_in[n_in - 6];
    const float* lin1_w = (const float*)d_in[n_in - 5];
    const float* lin2_w = (const float*)d_in[n_in - 4];
    const float* lin2_b = (const float*)d_in[n_in - 3];
    const float* lin_w  = (const float*)d_in[n_in - 2];
    const float* lin_b  = (const float*)d_in[n_in - 1];
    float* h = (float*)d_out;

    float *pG, *pCenv, *pHidden, *pTable, *pX, *pAgg;
    __half2* pT;
    __nv_bfloat16 *pW1h, *pW1l, *pW2h, *pW2l, *pL1h, *pL1l, *pL2h, *pL2l, *pLh, *pLl;
    cudaGetSymbolAddress((void**)&pG, g_G);
    cudaGetSymbolAddress((void**)&pCenv, g_Cenv);
    cudaGetSymbolAddress((void**)&pHidden, g_hidden);
    cudaGetSymbolAddress((void**)&pTable, g_table);
    cudaGetSymbolAddress((void**)&pX, g_x);
    cudaGetSymbolAddress((void**)&pAgg, g_agg);
    cudaGetSymbolAddress((void**)&pT, g_tph);
    cudaGetSymbolAddress((void**)&pW1h, g_w1T_hi); cudaGetSymbolAddress((void**)&pW1l, g_w1T_lo);
    cudaGetSymbolAddress((void**)&pW2h, g_w2T_hi); cudaGetSymbolAddress((void**)&pW2l, g_w2T_lo);
    cudaGetSymbolAddress((void**)&pL1h, g_l1T_hi); cudaGetSymbolAddress((void**)&pL1l, g_l1T_lo);
    cudaGetSymbolAddress((void**)&pL2h, g_l2T_hi); cudaGetSymbolAddress((void**)&pL2l, g_l2T_lo);
    cudaGetSymbolAddress((void**)&pLh,  g_lT_hi);  cudaGetSymbolAddress((void**)&pLl,  g_lT_lo);

    const int smem_agg = KCL * HID * 4 + KCL * 4 * 4 + 16 * 63 * 4 * 2;     // 74624
    cudaFuncSetAttribute(agg_k, cudaFuncAttributeMaxDynamicSharedMemorySize, smem_agg);
    const int smem_gemm = 2 * GBUF;                                          // 61440
    cudaFuncSetAttribute(gemm_k, cudaFuncAttributeMaxDynamicSharedMemorySize, smem_gemm);

    // ---- setup ----
    cg_k<<<MCL, 256>>>(pos, attr, sg, h);
    gauss_k<<<(TROWS * ECH + 255) / 256, 256>>>();

    // ---- weight transpose + split ----
    tsplit_k<<<dim3((ECH * FIL + 255) / 256, LINT), 256>>>(mlp_w1, pW1h, pW1l, ECH, FIL);
    tsplit_k<<<dim3((FIL * FIL + 255) / 256, LINT), 256>>>(mlp_w2, pW2h, pW2l, FIL, FIL);
    tsplit_k<<<dim3((HID * FIL + 255) / 256, LINT), 256>>>(lin1_w, pL1h, pL1l, HID, FIL);
    tsplit_k<<<dim3((FIL * HID + 255) / 256, LINT), 256>>>(lin2_w, pL2h, pL2l, FIL, HID);
    tsplit_k<<<dim3((HID * HID + 255) / 256, LINT), 256>>>(lin_w,  pLh,  pLl,  HID, HID);

    // ---- table build, batched over all 6 layers ----
    gemm_k<<<dim3(FIL / 64, TROWS / 128, LINT), 256, smem_gemm>>>(
        pG, pW1h, pW1l, mlp_b1, nullptr, nullptr, pHidden,
        FIL, ECH, OP_BIAS | OP_SSP,
        0, (size_t)FIL * ECH, FIL, (size_t)TROWS * FIL);
    gemm_k<<<dim3(FIL / 64, TROWS / 128, LINT), 256, smem_gemm>>>(
        pHidden, pW2h, pW2l, mlp_b2, pCenv, nullptr, pTable,
        FIL, FIL, OP_BIAS | OP_ROWS,
        (size_t)TROWS * FIL, (size_t)FIL * FIL, FIL, (size_t)TROWS * FIL);
    pack_k<<<(LINT * TROWS * FIL + 255) / 256, 256>>>();

    // ---- interaction layers ----
    for (int l = 0; l < LINT; l++) {
        gemm_k<<<dim3(FIL / 64, MCL / 128, 1), 256, smem_gemm>>>(
            h, pL1h + (size_t)l * HID * FIL, pL1l + (size_t)l * HID * FIL,
            nullptr, nullptr, nullptr, pX, FIL, HID, 0, 0, 0, 0, 0);
        agg_k<<<dim3(4, BG), 256, smem_agg>>>(pX, pT + (size_t)l * TROWS * FIL, pAgg);
        gemm_k<<<dim3(HID / 64, MCL / 128, 1), 256, smem_gemm>>>(
            pAgg, pL2h + (size_t)l * FIL * HID, pL2l + (size_t)l * FIL * HID,
            lin2_b + (size_t)l * HID, nullptr, nullptr, pX, HID, FIL,
            OP_BIAS | OP_SSP, 0, 0, 0, 0);
        gemm_k<<<dim3(HID / 64, MCL / 128, 1), 256, smem_gemm>>>(
            pX, pLh + (size_t)l * HID * HID, pLl + (size_t)l * HID * HID,
            lin_b + (size_t)l * HID, nullptr, h, h, HID, HID,
            OP_BIAS | OP_RES, 0, 0, 0, 0);
    }
}

// round 10
// speedup vs baseline: 1.4948x; 1.1433x over previous
#include <cuda_runtime.h>
#include <cuda_bf16.h>
#include <cuda_fp16.h>
#include <math.h>
#include <stdint.h>

#define NATOMS 16384
#define MCL    4096
#define BG     64
#define KCL    64
#define HID    256
#define FIL    256
#define ECH    64
#define LINT   6
#define TROWS  2048
#define TDELTA 0.005f
#define INV_TDELTA 200.0f
#define LN2F   0.69314718055994530942f
#define CUTOFF 10.0f

// -------- scratch (static device arrays; no cudaMalloc anywhere) --------
__device__ float g_pos4[MCL * 4];
__device__ float g_G[TROWS * ECH];
__device__ float g_Cenv[TROWS];
__device__ float g_hidden[LINT * TROWS * FIL];
__device__ float g_table[LINT * TROWS * FIL];
__device__ __half2 g_tph[LINT * TROWS * FIL];
__device__ float g_x[MCL * FIL];
__device__ float g_agg[MCL * FIL];

// transposed + hi/lo split weights (bf16), [L][N][K]
__device__ __nv_bfloat16 g_w1T_hi[LINT * FIL * ECH];
__device__ __nv_bfloat16 g_w1T_lo[LINT * FIL * ECH];
__device__ __nv_bfloat16 g_w2T_hi[LINT * FIL * FIL];
__device__ __nv_bfloat16 g_w2T_lo[LINT * FIL * FIL];
__device__ __nv_bfloat16 g_l1T_hi[LINT * HID * FIL];
__device__ __nv_bfloat16 g_l1T_lo[LINT * HID * FIL];
__device__ __nv_bfloat16 g_l2T_hi[LINT * FIL * HID];
__device__ __nv_bfloat16 g_l2T_lo[LINT * FIL * HID];
__device__ __nv_bfloat16 g_lT_hi[LINT * HID * HID];
__device__ __nv_bfloat16 g_lT_lo[LINT * HID * HID];

// ---------------- helpers ----------------
__device__ __forceinline__ uint32_t smem_u32(const void* p) {
    uint32_t a;
    asm("{ .reg .u64 t; cvta.to.shared.u64 t, %1; cvt.u32.u64 %0, t; }" : "=r"(a) : "l"(p));
    return a;
}
__device__ __forceinline__ float sspf(float x) {
    float ax = fabsf(x);
    return fmaxf(x, 0.f) + log1pf(expf(-ax)) - LN2F;
}
__device__ __forceinline__ bool sg_is64(const void* sg) {
    unsigned long long probe = ((const unsigned long long*)sg)[NATOMS / 2 - 1];
    return probe < (unsigned long long)MCL;
}
__device__ __forceinline__ int sg_at(const void* sg, int a, bool is64) {
    return is64 ? (int)((const long long*)sg)[a] : ((const int*)sg)[a];
}
__device__ __forceinline__ int lbound(const void* sg, bool is64, int val) {
    int lo = 0, hi = NATOMS;
    while (lo < hi) {
        int mid = (lo + hi) >> 1;
        if (sg_at(sg, mid, is64) < val) lo = mid + 1; else hi = mid;
    }
    return lo;
}
__device__ __forceinline__ uint32_t pack_bf2(__nv_bfloat16 a, __nv_bfloat16 b) {
    return ((uint32_t)__bfloat16_as_ushort(b) << 16) | (uint32_t)__bfloat16_as_ushort(a);
}

#define CP16(dst, src) \
    asm volatile("cp.async.cg.shared.global [%0], [%1], 16;" :: "r"(dst), "l"(src) : "memory")
#define CP_COMMIT() asm volatile("cp.async.commit_group;" ::: "memory")
#define CP_WAIT0()  asm volatile("cp.async.wait_group 0;" ::: "memory")
#define LDSM4(r, addr) \
    asm volatile("ldmatrix.sync.aligned.m8n8.x4.shared.b16 {%0,%1,%2,%3}, [%4];" \
        : "=r"((r)[0]), "=r"((r)[1]), "=r"((r)[2]), "=r"((r)[3]) : "r"(addr))
#define MMA_BF16(c, a, b0, b1) \
    asm volatile("mma.sync.aligned.m16n8k16.row.col.f32.bf16.bf16.f32 " \
        "{%0,%1,%2,%3}, {%4,%5,%6,%7}, {%8,%9}, {%0,%1,%2,%3};" \
        : "+f"((c)[0]), "+f"((c)[1]), "+f"((c)[2]), "+f"((c)[3]) \
        : "r"((a)[0]), "r"((a)[1]), "r"((a)[2]), "r"((a)[3]), "r"(b0), "r"(b1))

// ---------------- coarse grain: gather over contiguous sorted ranges ----------------
__global__ void __launch_bounds__(256) cg_k(const float* __restrict__ pos,
                                            const float* __restrict__ attr,
                                            const void* __restrict__ sg,
                                            float* __restrict__ h) {
    __shared__ int s_lo, s_hi;
    int c = blockIdx.x, f = threadIdx.x;
    bool is64 = sg_is64(sg);
    if (f == 0) s_lo = lbound(sg, is64, c);
    if (f == 1) s_hi = lbound(sg, is64, c + 1);
    __syncthreads();
    int lo = s_lo, hi = s_hi;
    float inv = 1.f / fmaxf((float)(hi - lo), 1.f);
    float s = 0.f;
    for (int a = lo; a < hi; a++) s += attr[(size_t)a * HID + f];
    h[(size_t)c * HID + f] = s * inv;
    if (f < 3) {
        float p = 0.f;
        for (int a = lo; a < hi; a++) p += pos[a * 3 + f];
        g_pos4[c * 4 + f] = p * inv;
    }
    if (f == 3) g_pos4[c * 4 + 3] = 0.f;
}

// ---------------- table-grid gaussians + cutoff envelope ----------------
__global__ void __launch_bounds__(256) gauss_k() {
    const float spacing = CUTOFF / 63.0f;
    const float coeff = -0.5f / (spacing * spacing);
    int t = blockIdx.x * 256 + threadIdx.x;
    if (t < TROWS * ECH) {
        int row = t >> 6, k = t & 63;
        float d = row * TDELTA;
        float u = d - (float)k * spacing;
        g_G[t] = expf(coeff * u * u);
    }
    if (t < TROWS) {
        float d = t * TDELTA;
        float c = (d <= CUTOFF) ? 0.5f * (cospif(d * (1.0f / CUTOFF)) + 1.0f) : 0.f;
        g_Cenv[t] = c;
    }
}

// tiled transpose + hi/lo split: in [L][R][C] fp32 -> out [L][C][R] bf16 hi/lo
__global__ void __launch_bounds__(256) tsplit_k(const float* __restrict__ in,
                                                __nv_bfloat16* __restrict__ hi,
                                                __nv_bfloat16* __restrict__ lo,
                                                int R, int C) {
    __shared__ float tile[32][33];
    int l = blockIdx.z;
    int c0 = blockIdx.x * 32, r0 = blockIdx.y * 32;
    int tx = threadIdx.x & 31, ty = threadIdx.x >> 5;   // 32 x 8
    const float* src = in + (size_t)l * R * C;
#pragma unroll
    for (int q = 0; q < 32; q += 8)
        tile[ty + q][tx] = src[(size_t)(r0 + ty + q) * C + c0 + tx];
    __syncthreads();
#pragma unroll
    for (int q = 0; q < 32; q += 8) {
        float v = tile[tx][ty + q];
        __nv_bfloat16 hh = __float2bfloat16(v);
        size_t o = (size_t)l * R * C + (size_t)(c0 + ty + q) * R + (r0 + tx);
        hi[o] = hh;
        lo[o] = __float2bfloat16(v - __bfloat162float(hh));
    }
}

// pack table rows into (T[i],T[i+1]) half2 pairs (all layers)
__global__ void __launch_bounds__(256) pack_k() {
    int t = blockIdx.x * 256 + threadIdx.x;
    if (t >= LINT * TROWS * FIL) return;
    int f = t & 255;
    int rest = t >> 8;                 // l*2048 + row
    int row = rest & (TROWS - 1);
    int l = rest >> 11;
    float a = g_table[t];
    int row2 = min(row + 1, TROWS - 1);
    float b = g_table[((size_t)l * TROWS + row2) * FIL + f];
    g_tph[t] = __floats2half2_rn(a, b);
}

// ---------------- HMMA bf16 split-precision GEMM ----------------
// C[M,N] = A[M,K] @ B[K,N]; A fp32 row-major; B pre-transposed+split bf16 [N][K].
// CTA tile 64x64 (4 warps, warp tile 32x32), KC=32 double-buffered.
#define OP_BIAS 1
#define OP_SSP  2
#define OP_ROWS 4
#define OP_RES  8

#define ASTR   80                       // smem row stride (bytes): 32 bf16 + 16B pad
#define A_BY   (64 * ASTR)              // 5120
#define OFF_AL A_BY
#define OFF_BH (2 * A_BY)
#define OFF_BL (3 * A_BY)
#define GBUF   (4 * A_BY)               // 20480

__device__ __forceinline__ void sts_a_split(char* buf, const float4* pref, int arow, int ahalf) {
    char* dh = buf + arow * ASTR + ahalf * 32;
#pragma unroll
    for (int q = 0; q < 4; q++) {
        float4 v = pref[q];
        __nv_bfloat16 h0 = __float2bfloat16(v.x), h1 = __float2bfloat16(v.y);
        __nv_bfloat16 h2 = __float2bfloat16(v.z), h3 = __float2bfloat16(v.w);
        __nv_bfloat16 l0 = __float2bfloat16(v.x - __bfloat162float(h0));
        __nv_bfloat16 l1 = __float2bfloat16(v.y - __bfloat162float(h1));
        __nv_bfloat16 l2 = __float2bfloat16(v.z - __bfloat162float(h2));
        __nv_bfloat16 l3 = __float2bfloat16(v.w - __bfloat162float(h3));
        *(uint2*)(dh + q * 8)          = make_uint2(pack_bf2(h0, h1), pack_bf2(h2, h3));
        *(uint2*)(dh + OFF_AL + q * 8) = make_uint2(pack_bf2(l0, l1), pack_bf2(l2, l3));
    }
}

__global__ void __launch_bounds__(128, 1)
gemm_k(const float* __restrict__ A,
       const __nv_bfloat16* __restrict__ Bhi, const __nv_bfloat16* __restrict__ Blo,
       const float* __restrict__ bias, const float* __restrict__ rowscale,
       const float* __restrict__ resid, float* __restrict__ C,
       int N, int K, int ops,
       size_t zA, size_t zB, size_t zBias, size_t zC) {
    extern __shared__ __align__(16) char sm[];
    int z = blockIdx.z;
    A += (size_t)z * zA; Bhi += (size_t)z * zB; Blo += (size_t)z * zB;
    C += (size_t)z * zC;
    const float* biasz = bias ? bias + (size_t)z * zBias : (const float*)0;

    int tid = threadIdx.x;
    int lane = tid & 31, wid = tid >> 5;     // 4 warps
    int wm = wid >> 1, wn = wid & 1;         // 2x2 warp grid, 32x32 each
    int bm = blockIdx.y, bn = blockIdx.x;
    uint32_t smu = smem_u32(sm);

    // staging coords: A 64 rows x 32 floats per chunk
    int arow = tid >> 1, ahalf = tid & 1;
    const float* aptr = A + (size_t)(bm * 64 + arow) * K + ahalf * 16;
    // B 64 rows x 32 bf16 per chunk; thread covers rows brow and brow+32
    int brow = tid >> 2, bseg = tid & 3;
    const __nv_bfloat16* bhp = Bhi + (size_t)(bn * 64 + brow) * K + bseg * 8;
    const __nv_bfloat16* blp = Blo + (size_t)(bn * 64 + brow) * K + bseg * 8;
    size_t brstride = (size_t)32 * K;
    uint32_t bdst = brow * ASTR + bseg * 16;

    float acc[2][4][4];
#pragma unroll
    for (int i = 0; i < 2; i++)
#pragma unroll
        for (int j = 0; j < 4; j++)
#pragma unroll
            for (int q = 0; q < 4; q++) acc[i][j][q] = 0.f;

    int NC = K >> 5;
    float4 pref[4];

    // prologue: stage chunk 0 into buffer 0
    {
        pref[0] = *(const float4*)(aptr + 0);
        pref[1] = *(const float4*)(aptr + 4);
        pref[2] = *(const float4*)(aptr + 8);
        pref[3] = *(const float4*)(aptr + 12);
        CP16(smu + OFF_BH + bdst, bhp);
        CP16(smu + OFF_BH + bdst + 32 * ASTR, bhp + brstride);
        CP16(smu + OFF_BL + bdst, blp);
        CP16(smu + OFF_BL + bdst + 32 * ASTR, blp + brstride);
        CP_COMMIT();
        sts_a_split(sm, pref, arow, ahalf);
        CP_WAIT0();
        __syncthreads();
    }

    for (int c = 0; c < NC; c++) {
        uint32_t cur = smu + (c & 1) * GBUF;
        char* nxtp = sm + ((c + 1) & 1) * GBUF;
        uint32_t nxtu = smu + ((c + 1) & 1) * GBUF;
        if (c + 1 < NC) {
            int kc = (c + 1) * 32;
            const float* p = aptr + kc;
            pref[0] = *(const float4*)(p + 0);
            pref[1] = *(const float4*)(p + 4);
            pref[2] = *(const float4*)(p + 8);
            pref[3] = *(const float4*)(p + 12);
            CP16(nxtu + OFF_BH + bdst, bhp + kc);
            CP16(nxtu + OFF_BH + bdst + 32 * ASTR, bhp + brstride + kc);
            CP16(nxtu + OFF_BL + bdst, blp + kc);
            CP16(nxtu + OFF_BL + bdst + 32 * ASTR, blp + brstride + kc);
            CP_COMMIT();
        }
        // ---- compute from cur ----
#pragma unroll
        for (int ks = 0; ks < 2; ks++) {
            uint32_t ah[2][4], al[2][4];
#pragma unroll
            for (int mt = 0; mt < 2; mt++) {
                uint32_t addr = cur + (wm * 32 + mt * 16 + (lane & 15)) * ASTR
                              + ks * 32 + (lane >> 4) * 16;
                LDSM4(ah[mt], addr);
                LDSM4(al[mt], addr + OFF_AL);
            }
            uint32_t bh[2][4], bl[2][4];
#pragma unroll
            for (int pr = 0; pr < 2; pr++) {
                uint32_t addr = cur + OFF_BH + (wn * 32 + pr * 16 + (lane & 15)) * ASTR
                              + ks * 32 + (lane >> 4) * 16;
                LDSM4(bh[pr], addr);
                LDSM4(bl[pr], addr + A_BY);   // BL is A_BY past BH
            }
#pragma unroll
            for (int mt = 0; mt < 2; mt++)
#pragma unroll
                for (int nt = 0; nt < 4; nt++) {
                    float* cc = acc[mt][nt];
                    uint32_t bh0 = bh[nt >> 1][nt & 1], bh1 = bh[nt >> 1][2 + (nt & 1)];
                    uint32_t bl0 = bl[nt >> 1][nt & 1], bl1 = bl[nt >> 1][2 + (nt & 1)];
                    MMA_BF16(cc, ah[mt], bh0, bh1);
                    MMA_BF16(cc, ah[mt], bl0, bl1);
                    MMA_BF16(cc, al[mt], bh0, bh1);
                }
        }
        if (c + 1 < NC) {
            CP_WAIT0();
            sts_a_split(nxtp, pref, arow, ahalf);
        }
        __syncthreads();
    }

    // ---- epilogue ----
    int lr = lane >> 2, lc = (lane & 3) * 2;
#pragma unroll
    for (int mt = 0; mt < 2; mt++) {
#pragma unroll
        for (int half = 0; half < 2; half++) {
            int row = bm * 64 + wm * 32 + mt * 16 + half * 8 + lr;
            float rs = (ops & OP_ROWS) ? rowscale[row] : 1.f;
#pragma unroll
            for (int nt = 0; nt < 4; nt++) {
                int col = bn * 64 + wn * 32 + nt * 8 + lc;
                float v0 = acc[mt][nt][half * 2 + 0];
                float v1 = acc[mt][nt][half * 2 + 1];
                if (ops & OP_BIAS) {
                    float2 b = *(const float2*)(biasz + col);
                    v0 += b.x; v1 += b.y;
                }
                if (ops & OP_SSP) { v0 = sspf(v0); v1 = sspf(v1); }
                if (ops & OP_ROWS) { v0 *= rs; v1 *= rs; }
                size_t o = (size_t)row * N + col;
                if (ops & OP_RES) {
                    float2 r = *(const float2*)(resid + o);
                    v0 += r.x; v1 += r.y;
                }
                *(float2*)(C + o) = make_float2(v0, v1);
            }
        }
    }
}

// ---------------- fused edge aggregation (half2 table lerp) ----------------
// grid: (8 dest-blocks of 8, 64 graphs), 256 threads (thread = feature)
__global__ void __launch_bounds__(256) agg_k(const float* __restrict__ x,
                                             const __half2* __restrict__ T2,
                                             float* __restrict__ agg) {
    extern __shared__ float smf[];
    float* sx   = smf;                                   // 64*256
    float* spos = smf + KCL * HID;                       // 64*4
    int*   sidx = (int*)(smf + KCL * HID + KCL * 4);     // 8*63
    float* st   = smf + KCL * HID + KCL * 4 + 8 * 63;    // 8*63

    int g  = blockIdx.y;
    int jb = blockIdx.x;
    int tid = threadIdx.x;

    const float* xg = x + (size_t)g * KCL * HID;
    for (int k = tid; k < KCL * HID; k += 256) sx[k] = xg[k];
    if (tid < KCL * 4) spos[tid] = g_pos4[g * KCL * 4 + tid];
    __syncthreads();

    for (int e = tid; e < 8 * 63; e += 256) {
        int j = jb * 8 + e / 63;
        int ii = e % 63;
        int i = ii + (ii >= j);
        float dx = spos[j * 4 + 0] - spos[i * 4 + 0];
        float dy = spos[j * 4 + 1] - spos[i * 4 + 1];
        float dz = spos[j * 4 + 2] - spos[i * 4 + 2];
        float d = sqrtf(dx * dx + dy * dy + dz * dz);
        float u = d * INV_TDELTA;
        int idx = (int)u;
        if (idx > TROWS - 2) idx = TROWS - 2;
        sidx[e] = idx;
        st[e] = u - (float)idx;
    }
    __syncthreads();

    int f = tid;
#pragma unroll 1
    for (int jj = 0; jj < 8; jj++) {
        int j = jb * 8 + jj;
        int ebase = jj * 63;
        float acc = 0.f;
#pragma unroll 7
        for (int ii = 0; ii < 63; ii++) {
            int e = ebase + ii;
            int i = ii + (ii >= j);
            float2 p = __half22float2(T2[(size_t)sidx[e] * FIL + f]);
            float w = p.x + st[e] * (p.y - p.x);
            acc = fmaf(sx[i * HID + f], w, acc);
        }
        agg[((size_t)g * KCL + j) * FIL + f] = acc;
    }
}

extern "C" void kernel_launch(void* const* d_in, const int* in_sizes, int n_in,
                              void* d_out, int out_size) {
    const float* pos  = (const float*)d_in[0];
    const float* attr = (const float*)d_in[1];
    const void*  sg   = d_in[2];
    const float* mlp_w1 = (const float*)d_in[n_in - 9];
    const float* mlp_b1 = (const float*)d_in[n_in - 8];
    const float* mlp_w2 = (const float*)d_in[n_in - 7];
    const float* mlp_b2 = (const float*)d_in[n_in - 6];
    const float* lin1_w = (const float*)d_in[n_in - 5];
    const float* lin2_w = (const float*)d_in[n_in - 4];
    const float* lin2_b = (const float*)d_in[n_in - 3];
    const float* lin_w  = (const float*)d_in[n_in - 2];
    const float* lin_b  = (const float*)d_in[n_in - 1];
    float* h = (float*)d_out;

    float *pG, *pCenv, *pHidden, *pTable, *pX, *pAgg;
    __half2* pT;
    __nv_bfloat16 *pW1h, *pW1l, *pW2h, *pW2l, *pL1h, *pL1l, *pL2h, *pL2l, *pLh, *pLl;
    cudaGetSymbolAddress((void**)&pG, g_G);
    cudaGetSymbolAddress((void**)&pCenv, g_Cenv);
    cudaGetSymbolAddress((void**)&pHidden, g_hidden);
    cudaGetSymbolAddress((void**)&pTable, g_table);
    cudaGetSymbolAddress((void**)&pX, g_x);
    cudaGetSymbolAddress((void**)&pAgg, g_agg);
    cudaGetSymbolAddress((void**)&pT, g_tph);
    cudaGetSymbolAddress((void**)&pW1h, g_w1T_hi); cudaGetSymbolAddress((void**)&pW1l, g_w1T_lo);
    cudaGetSymbolAddress((void**)&pW2h, g_w2T_hi); cudaGetSymbolAddress((void**)&pW2l, g_w2T_lo);
    cudaGetSymbolAddress((void**)&pL1h, g_l1T_hi); cudaGetSymbolAddress((void**)&pL1l, g_l1T_lo);
    cudaGetSymbolAddress((void**)&pL2h, g_l2T_hi); cudaGetSymbolAddress((void**)&pL2l, g_l2T_lo);
    cudaGetSymbolAddress((void**)&pLh,  g_lT_hi);  cudaGetSymbolAddress((void**)&pLl,  g_lT_lo);

    const int smem_agg = KCL * HID * 4 + KCL * 4 * 4 + 8 * 63 * 4 * 2;      // 70656
    cudaFuncSetAttribute(agg_k, cudaFuncAttributeMaxDynamicSharedMemorySize, smem_agg);
    const int smem_gemm = 2 * GBUF;                                          // 40960
    cudaFuncSetAttribute(gemm_k, cudaFuncAttributeMaxDynamicSharedMemorySize, smem_gemm);

    // ---- setup ----
    cg_k<<<MCL, 256>>>(pos, attr, sg, h);
    gauss_k<<<(TROWS * ECH + 255) / 256, 256>>>();

    // ---- weight transpose + split (tiled, coalesced) ----
    tsplit_k<<<dim3(FIL / 32, ECH / 32, LINT), 256>>>(mlp_w1, pW1h, pW1l, ECH, FIL);
    tsplit_k<<<dim3(FIL / 32, FIL / 32, LINT), 256>>>(mlp_w2, pW2h, pW2l, FIL, FIL);
    tsplit_k<<<dim3(FIL / 32, HID / 32, LINT), 256>>>(lin1_w, pL1h, pL1l, HID, FIL);
    tsplit_k<<<dim3(HID / 32, FIL / 32, LINT), 256>>>(lin2_w, pL2h, pL2l, FIL, HID);
    tsplit_k<<<dim3(HID / 32, HID / 32, LINT), 256>>>(lin_w,  pLh,  pLl,  HID, HID);

    // ---- table build, batched over all 6 layers ----
    gemm_k<<<dim3(FIL / 64, TROWS / 64, LINT), 128, smem_gemm>>>(
        pG, pW1h, pW1l, mlp_b1, nullptr, nullptr, pHidden,
        FIL, ECH, OP_BIAS | OP_SSP,
        0, (size_t)FIL * ECH, FIL, (size_t)TROWS * FIL);
    gemm_k<<<dim3(FIL / 64, TROWS / 64, LINT), 128, smem_gemm>>>(
        pHidden, pW2h, pW2l, mlp_b2, pCenv, nullptr, pTable,
        FIL, FIL, OP_BIAS | OP_ROWS,
        (size_t)TROWS * FIL, (size_t)FIL * FIL, FIL, (size_t)TROWS * FIL);
    pack_k<<<(LINT * TROWS * FIL + 255) / 256, 256>>>();

    // ---- interaction layers ----
    for (int l = 0; l < LINT; l++) {
        gemm_k<<<dim3(FIL / 64, MCL / 64, 1), 128, smem_gemm>>>(
            h, pL1h + (size_t)l * HID * FIL, pL1l + (size_t)l * HID * FIL,
            nullptr, nullptr, nullptr, pX, FIL, HID, 0, 0, 0, 0, 0);
        agg_k<<<dim3(8, BG), 256, smem_agg>>>(pX, pT + (size_t)l * TROWS * FIL, pAgg);
        gemm_k<<<dim3(HID / 64, MCL / 64, 1), 128, smem_gemm>>>(
            pAgg, pL2h + (size_t)l * FIL * HID, pL2l + (size_t)l * FIL * HID,
            lin2_b + (size_t)l * HID, nullptr, nullptr, pX, HID, FIL,
            OP_BIAS | OP_SSP, 0, 0, 0, 0);
        gemm_k<<<dim3(HID / 64, MCL / 64, 1), 128, smem_gemm>>>(
            pX, pLh + (size_t)l * HID * HID, pLl + (size_t)l * HID * HID,
            lin_b + (size_t)l * HID, nullptr, h, h, HID, HID,
            OP_BIAS | OP_RES, 0, 0, 0, 0);
    }
}

// round 13
// speedup vs baseline: 1.7594x; 1.1770x over previous
#include <cuda_runtime.h>
#include <cuda_bf16.h>
#include <cuda_fp16.h>
#include <math.h>
#include <stdint.h>

#define NATOMS 16384
#define MCL    4096
#define BG     64
#define KCL    64
#define HID    256
#define FIL    256
#define ECH    64
#define LINT   6
#define TROWS  2048
#define TDELTA 0.005f
#define INV_TDELTA 200.0f
#define LN2F   0.69314718055994530942f
#define CUTOFF 10.0f

// -------- scratch (static device arrays; no cudaMalloc anywhere) --------
__device__ float g_pos4[MCL * 4];
__device__ float g_G[TROWS * ECH];
__device__ float g_Cenv[TROWS];
__device__ float g_hidden[LINT * TROWS * FIL];
__device__ float g_table[LINT * TROWS * FIL];
__device__ __half2 g_tph[LINT * TROWS * FIL];
__device__ float g_x2[MCL * FIL];
__device__ float g_agg[MCL * FIL];

// transposed + hi/lo split weights (bf16), [L][N][K]
__device__ __nv_bfloat16 g_w1T_hi[LINT * FIL * ECH];
__device__ __nv_bfloat16 g_w1T_lo[LINT * FIL * ECH];
__device__ __nv_bfloat16 g_w2T_hi[LINT * FIL * FIL];
__device__ __nv_bfloat16 g_w2T_lo[LINT * FIL * FIL];
__device__ __nv_bfloat16 g_l1T_hi[LINT * HID * FIL];
__device__ __nv_bfloat16 g_l1T_lo[LINT * HID * FIL];
__device__ __nv_bfloat16 g_l2T_hi[LINT * FIL * HID];
__device__ __nv_bfloat16 g_l2T_lo[LINT * FIL * HID];
__device__ __nv_bfloat16 g_lT_hi[LINT * HID * HID];
__device__ __nv_bfloat16 g_lT_lo[LINT * HID * HID];

// ---------------- helpers ----------------
__device__ __forceinline__ uint32_t smem_u32(const void* p) {
    uint32_t a;
    asm("{ .reg .u64 t; cvta.to.shared.u64 t, %1; cvt.u32.u64 %0, t; }" : "=r"(a) : "l"(p));
    return a;
}
__device__ __forceinline__ float sspf(float x) {
    float ax = fabsf(x);
    return fmaxf(x, 0.f) + log1pf(expf(-ax)) - LN2F;
}
__device__ __forceinline__ bool sg_is64(const void* sg) {
    unsigned long long probe = ((const unsigned long long*)sg)[NATOMS / 2 - 1];
    return probe < (unsigned long long)MCL;
}
__device__ __forceinline__ int sg_at(const void* sg, int a, bool is64) {
    return is64 ? (int)((const long long*)sg)[a] : ((const int*)sg)[a];
}
__device__ __forceinline__ int lbound(const void* sg, bool is64, int val) {
    int lo = 0, hi = NATOMS;
    while (lo < hi) {
        int mid = (lo + hi) >> 1;
        if (sg_at(sg, mid, is64) < val) lo = mid + 1; else hi = mid;
    }
    return lo;
}
__device__ __forceinline__ uint32_t pack_bf2(__nv_bfloat16 a, __nv_bfloat16 b) {
    return ((uint32_t)__bfloat16_as_ushort(b) << 16) | (uint32_t)__bfloat16_as_ushort(a);
}

#define CP16(dst, src) \
    asm volatile("cp.async.cg.shared.global [%0], [%1], 16;" :: "r"(dst), "l"(src) : "memory")
#define CP_COMMIT() asm volatile("cp.async.commit_group;" ::: "memory")
#define CP_WAIT0()  asm volatile("cp.async.wait_group 0;" ::: "memory")
#define LDSM4(r, addr) \
    asm volatile("ldmatrix.sync.aligned.m8n8.x4.shared.b16 {%0,%1,%2,%3}, [%4];" \
        : "=r"((r)[0]), "=r"((r)[1]), "=r"((r)[2]), "=r"((r)[3]) : "r"(addr))
#define MMA_BF16(c, a, b0, b1) \
    asm volatile("mma.sync.aligned.m16n8k16.row.col.f32.bf16.bf16.f32 " \
        "{%0,%1,%2,%3}, {%4,%5,%6,%7}, {%8,%9}, {%0,%1,%2,%3};" \
        : "+f"((c)[0]), "+f"((c)[1]), "+f"((c)[2]), "+f"((c)[3]) \
        : "r"((a)[0]), "r"((a)[1]), "r"((a)[2]), "r"((a)[3]), "r"(b0), "r"(b1))

// ---------------- setup: coarse-grain + table-grid gaussians, one launch ----------------
__global__ void __launch_bounds__(256) setup_k(const float* __restrict__ pos,
                                               const float* __restrict__ attr,
                                               const void* __restrict__ sg,
                                               float* __restrict__ h) {
    if (blockIdx.x < MCL) {
        __shared__ int s_lo, s_hi;
        int c = blockIdx.x, f = threadIdx.x;
        bool is64 = sg_is64(sg);
        if (f == 0) s_lo = lbound(sg, is64, c);
        if (f == 1) s_hi = lbound(sg, is64, c + 1);
        __syncthreads();
        int lo = s_lo, hi = s_hi;
        float inv = 1.f / fmaxf((float)(hi - lo), 1.f);
        float s = 0.f;
        for (int a = lo; a < hi; a++) s += attr[(size_t)a * HID + f];
        h[(size_t)c * HID + f] = s * inv;
        if (f < 3) {
            float p = 0.f;
            for (int a = lo; a < hi; a++) p += pos[a * 3 + f];
            g_pos4[c * 4 + f] = p * inv;
        }
        if (f == 3) g_pos4[c * 4 + 3] = 0.f;
    } else {
        const float spacing = CUTOFF / 63.0f;
        const float coeff = -0.5f / (spacing * spacing);
        int t = (blockIdx.x - MCL) * 256 + threadIdx.x;
        if (t < TROWS * ECH) {
            int row = t >> 6, k = t & 63;
            float d = row * TDELTA;
            float u = d - (float)k * spacing;
            g_G[t] = expf(coeff * u * u);
        }
        if (t < TROWS) {
            float d = t * TDELTA;
            float c = (d <= CUTOFF) ? 0.5f * (cospif(d * (1.0f / CUTOFF)) + 1.0f) : 0.f;
            g_Cenv[t] = c;
        }
    }
}

// ---------------- all weight transposes + hi/lo split in one launch ----------------
__global__ void __launch_bounds__(256) tsplit_k(const float* __restrict__ w1,
                                                const float* __restrict__ w2,
                                                const float* __restrict__ l1w,
                                                const float* __restrict__ l2w,
                                                const float* __restrict__ lw) {
    __shared__ float tile[32][33];
    int z = blockIdx.z;
    int l = z / 5, w = z % 5;
    const float* src; __nv_bfloat16 *hi, *lo; int R, C;
    switch (w) {
        case 0: src = w1;  hi = g_w1T_hi; lo = g_w1T_lo; R = ECH; C = FIL; break;
        case 1: src = w2;  hi = g_w2T_hi; lo = g_w2T_lo; R = FIL; C = FIL; break;
        case 2: src = l1w; hi = g_l1T_hi; lo = g_l1T_lo; R = HID; C = FIL; break;
        case 3: src = l2w; hi = g_l2T_hi; lo = g_l2T_lo; R = FIL; C = HID; break;
        default: src = lw; hi = g_lT_hi;  lo = g_lT_lo;  R = HID; C = HID; break;
    }
    int c0 = blockIdx.x * 32, r0 = blockIdx.y * 32;
    if (r0 >= R || c0 >= C) return;
    src += (size_t)l * R * C;
    int tx = threadIdx.x & 31, ty = threadIdx.x >> 5;
#pragma unroll
    for (int q = 0; q < 32; q += 8)
        tile[ty + q][tx] = src[(size_t)(r0 + ty + q) * C + c0 + tx];
    __syncthreads();
#pragma unroll
    for (int q = 0; q < 32; q += 8) {
        float v = tile[tx][ty + q];
        __nv_bfloat16 hh = __float2bfloat16(v);
        size_t o = (size_t)l * R * C + (size_t)(c0 + ty + q) * R + (r0 + tx);
        hi[o] = hh;
        lo[o] = __float2bfloat16(v - __bfloat162float(hh));
    }
}

// pack table rows into (T[i],T[i+1]) half2 pairs (all layers)
__global__ void __launch_bounds__(256) pack_k() {
    int t = blockIdx.x * 256 + threadIdx.x;
    if (t >= LINT * TROWS * FIL) return;
    int f = t & 255;
    int rest = t >> 8;
    int row = rest & (TROWS - 1);
    int l = rest >> 11;
    float a = g_table[t];
    int row2 = min(row + 1, TROWS - 1);
    float b = g_table[((size_t)l * TROWS + row2) * FIL + f];
    g_tph[t] = __floats2half2_rn(a, b);
}

// ---------------- HMMA bf16 split-precision GEMM core ----------------
// CTA tile 64x64, 256 threads (8 warps, warp tile 16x32), KC=32 double-buffered.
#define OP_BIAS 1
#define OP_SSP  2
#define OP_ROWS 4
#define OP_RES  8

#define ASTR   80
#define A_BY   (64 * ASTR)              // 5120
#define OFF_AL A_BY
#define OFF_BH (2 * A_BY)
#define OFF_BL (3 * A_BY)
#define GBUF   (4 * A_BY)               // 20480
#define SMEM_G (2 * GBUF)               // 40960

__device__ __forceinline__ void sts_a_split(char* buf, const float4* pref, int arow, int aseg) {
    char* dh = buf + arow * ASTR + aseg * 16;
#pragma unroll
    for (int q = 0; q < 2; q++) {
        float4 v = pref[q];
        __nv_bfloat16 h0 = __float2bfloat16(v.x), h1 = __float2bfloat16(v.y);
        __nv_bfloat16 h2 = __float2bfloat16(v.z), h3 = __float2bfloat16(v.w);
        __nv_bfloat16 l0 = __float2bfloat16(v.x - __bfloat162float(h0));
        __nv_bfloat16 l1 = __float2bfloat16(v.y - __bfloat162float(h1));
        __nv_bfloat16 l2 = __float2bfloat16(v.z - __bfloat162float(h2));
        __nv_bfloat16 l3 = __float2bfloat16(v.w - __bfloat162float(h3));
        *(uint2*)(dh + q * 8)          = make_uint2(pack_bf2(h0, h1), pack_bf2(h2, h3));
        *(uint2*)(dh + OFF_AL + q * 8) = make_uint2(pack_bf2(l0, l1), pack_bf2(l2, l3));
    }
}

// core mainloop: leaves 16 accumulators per thread (warp tile 16x32)
// acc[nt][q]: nt = 8-col group within warp's 32 cols, q = row-frag
__device__ __forceinline__ void gemm_core(char* sm, uint32_t smu,
                                          const float* A, const __nv_bfloat16* Bhi,
                                          const __nv_bfloat16* Blo,
                                          int arow_base, int brow_base, int K,
                                          float acc[4][4]) {
    int tid = threadIdx.x;
    int lane = tid & 31, wid = tid >> 5;
    int wm = wid >> 1, wn = wid & 1;

    int arow = tid >> 2, aseg = tid & 3;
    const float* aptr = A + (size_t)(arow_base + arow) * K + aseg * 8;
    int brow = tid >> 2, bseg = tid & 3;
    const __nv_bfloat16* bhp = Bhi + (size_t)(brow_base + brow) * K + bseg * 8;
    const __nv_bfloat16* blp = Blo + (size_t)(brow_base + brow) * K + bseg * 8;
    uint32_t bdst = brow * ASTR + bseg * 16;

    int NC = K >> 5;
    float4 pref[2];

    // prologue
    pref[0] = *(const float4*)(aptr + 0);
    pref[1] = *(const float4*)(aptr + 4);
    CP16(smu + OFF_BH + bdst, bhp);
    CP16(smu + OFF_BL + bdst, blp);
    CP_COMMIT();
    sts_a_split(sm, pref, arow, aseg);
    CP_WAIT0();
    __syncthreads();

    for (int c = 0; c < NC; c++) {
        uint32_t cur = smu + (c & 1) * GBUF;
        char* nxtp = sm + ((c + 1) & 1) * GBUF;
        uint32_t nxtu = smu + ((c + 1) & 1) * GBUF;
        if (c + 1 < NC) {
            int kc = (c + 1) * 32;
            const float* p = aptr + kc;
            pref[0] = *(const float4*)(p + 0);
            pref[1] = *(const float4*)(p + 4);
            CP16(nxtu + OFF_BH + bdst, bhp + kc);
            CP16(nxtu + OFF_BL + bdst, blp + kc);
            CP_COMMIT();
        }
#pragma unroll
        for (int ks = 0; ks < 2; ks++) {
            uint32_t ah[4], al[4];
            uint32_t addrA = cur + (wm * 16 + (lane & 15)) * ASTR + ks * 32 + (lane >> 4) * 16;
            LDSM4(ah, addrA);
            LDSM4(al, addrA + OFF_AL);
            uint32_t bh[2][4], bl[2][4];
#pragma unroll
            for (int pr = 0; pr < 2; pr++) {
                uint32_t addrB = cur + OFF_BH + (wn * 32 + pr * 16 + (lane & 15)) * ASTR
                               + ks * 32 + (lane >> 4) * 16;
                LDSM4(bh[pr], addrB);
                LDSM4(bl[pr], addrB + A_BY);
            }
#pragma unroll
            for (int nt = 0; nt < 4; nt++) {
                float* cc = acc[nt];
                uint32_t bh0 = bh[nt >> 1][nt & 1], bh1 = bh[nt >> 1][2 + (nt & 1)];
                uint32_t bl0 = bl[nt >> 1][nt & 1], bl1 = bl[nt >> 1][2 + (nt & 1)];
                MMA_BF16(cc, ah, bh0, bh1);
                MMA_BF16(cc, ah, bl0, bl1);
                MMA_BF16(cc, al, bh0, bh1);
            }
        }
        if (c + 1 < NC) {
            CP_WAIT0();
            sts_a_split(nxtp, pref, arow, aseg);
        }
        __syncthreads();
    }
}

// ---------------- standalone GEMM with fused epilogue ----------------
__global__ void __launch_bounds__(256)
gemm_k(const float* __restrict__ A,
       const __nv_bfloat16* __restrict__ Bhi, const __nv_bfloat16* __restrict__ Blo,
       const float* __restrict__ bias, const float* __restrict__ rowscale,
       const float* __restrict__ resid, float* __restrict__ C,
       int N, int K, int ops,
       size_t zA, size_t zB, size_t zBias, size_t zC) {
    extern __shared__ __align__(16) char sm[];
    int z = blockIdx.z;
    A += (size_t)z * zA; Bhi += (size_t)z * zB; Blo += (size_t)z * zB;
    C += (size_t)z * zC;
    const float* biasz = bias ? bias + (size_t)z * zBias : (const float*)0;

    int bm = blockIdx.y, bn = blockIdx.x;
    float acc[4][4];
#pragma unroll
    for (int j = 0; j < 4; j++)
#pragma unroll
        for (int q = 0; q < 4; q++) acc[j][q] = 0.f;

    gemm_core(sm, smem_u32(sm), A, Bhi, Blo, bm * 64, bn * 64, K, acc);

    int lane = threadIdx.x & 31, wid = threadIdx.x >> 5;
    int wm = wid >> 1, wn = wid & 1;
    int lr = lane >> 2, lc = (lane & 3) * 2;
#pragma unroll
    for (int half = 0; half < 2; half++) {
        int row = bm * 64 + wm * 16 + half * 8 + lr;
        float rs = (ops & OP_ROWS) ? rowscale[row] : 1.f;
#pragma unroll
        for (int nt = 0; nt < 4; nt++) {
            int col = bn * 64 + wn * 32 + nt * 8 + lc;
            float v0 = acc[nt][half * 2 + 0];
            float v1 = acc[nt][half * 2 + 1];
            if (ops & OP_BIAS) {
                float2 b = *(const float2*)(biasz + col);
                v0 += b.x; v1 += b.y;
            }
            if (ops & OP_SSP) { v0 = sspf(v0); v1 = sspf(v1); }
            if (ops & OP_ROWS) { v0 *= rs; v1 *= rs; }
            size_t o = (size_t)row * N + col;
            if (ops & OP_RES) {
                float2 r = *(const float2*)(resid + o);
                v0 += r.x; v1 += r.y;
            }
            *(float2*)(C + o) = make_float2(v0, v1);
        }
    }
}

// ---------------- fused lin1 + edge aggregation ----------------
// grid: (4 feature-blocks of 64, 64 graphs); 256 threads.
// Phase 1: x_tile[64 clusters][64 feats] = h_g @ lin1[:, fb]   (HMMA, into smem)
// Phase 2: agg[j][f] = sum_i lerp(T, d_ij)[f] * x[i][f]        (table in L2)
__global__ void __launch_bounds__(256)
linagg_k(const float* __restrict__ h,
         const __nv_bfloat16* __restrict__ Bhi, const __nv_bfloat16* __restrict__ Blo,
         const __half2* __restrict__ T2, float* __restrict__ agg) {
    extern __shared__ __align__(16) char sm[];
    int g = blockIdx.y, fb = blockIdx.x;
    int tid = threadIdx.x;

    float acc[4][4];
#pragma unroll
    for (int j = 0; j < 4; j++)
#pragma unroll
        for (int q = 0; q < 4; q++) acc[j][q] = 0.f;

    gemm_core(sm, smem_u32(sm), h, Bhi, Blo, g * 64, fb * 64, HID, acc);

    // phase-2 smem layout (overlaps dead gemm buffers)
    float* sx   = (float*)sm;                     // 64 x 64
    float* spos = (float*)(sm + 16384);           // 64 x 4
    uint32_t* meta = (uint32_t*)(sm + 17408);     // 4032

    // write x tile to smem
    {
        int lane = tid & 31, wid = tid >> 5;
        int wm = wid >> 1, wn = wid & 1;
        int lr = lane >> 2, lc = (lane & 3) * 2;
#pragma unroll
        for (int half = 0; half < 2; half++) {
            int row = wm * 16 + half * 8 + lr;
#pragma unroll
            for (int nt = 0; nt < 4; nt++) {
                int col = wn * 32 + nt * 8 + lc;
                *(float2*)(sx + row * 64 + col) =
                    make_float2(acc[nt][half * 2 + 0], acc[nt][half * 2 + 1]);
            }
        }
    }
    if (tid < 256) spos[tid] = g_pos4[g * 256 + tid];
    __syncthreads();

    // per-edge table index + frac
    for (int e = tid; e < KCL * 63; e += 256) {
        int j = e / 63;
        int ii = e % 63;
        int i = ii + (ii >= j);
        float dx = spos[j * 4 + 0] - spos[i * 4 + 0];
        float dy = spos[j * 4 + 1] - spos[i * 4 + 1];
        float dz = spos[j * 4 + 2] - spos[i * 4 + 2];
        float d = sqrtf(dx * dx + dy * dy + dz * dz);
        float u = d * INV_TDELTA;
        int idx = (int)u;
        if (idx > TROWS - 2) idx = TROWS - 2;
        __half hf = __float2half_rn(u - (float)idx);
        meta[e] = ((uint32_t)idx << 16) | (uint32_t)__half_as_ushort(hf);
    }
    __syncthreads();

    int f = tid & 63;
    int dh = tid >> 6;      // dest quarter
    int fbase = fb * 64;
#pragma unroll 1
    for (int jj = 0; jj < 16; jj++) {
        int j = dh * 16 + jj;
        int ebase = j * 63;
        float a = 0.f;
#pragma unroll 7
        for (int ii = 0; ii < 63; ii++) {
            int e = ebase + ii;
            int i = ii + (ii >= j);
            uint32_t m = meta[e];
            int idx = m >> 16;
            float fr = __half2float(__ushort_as_half((unsigned short)(m & 0xffffu)));
            float2 p = __half22float2(T2[(size_t)idx * FIL + fbase + f]);
            float w = p.x + fr * (p.y - p.x);
            a = fmaf(sx[i * 64 + f], w, a);
        }
        agg[((size_t)g * KCL + j) * FIL + fbase + f] = a;
    }
}

extern "C" void kernel_launch(void* const* d_in, const int* in_sizes, int n_in,
                              void* d_out, int out_size) {
    const float* pos  = (const float*)d_in[0];
    const float* attr = (const float*)d_in[1];
    const void*  sg   = d_in[2];
    const float* mlp_w1 = (const float*)d_in[n_in - 9];
    const float* mlp_b1 = (const float*)d_in[n_in - 8];
    const float* mlp_w2 = (const float*)d_in[n_in - 7];
    const float* mlp_b2 = (const float*)d_in[n_in - 6];
    const float* lin1_w = (const float*)d_in[n_in - 5];
    const float* lin2_w = (const float*)d_in[n_in - 4];
    const float* lin2_b = (const float*)d_in[n_in - 3];
    const float* lin_w  = (const float*)d_in[n_in - 2];
    const float* lin_b  = (const float*)d_in[n_in - 1];
    float* h = (float*)d_out;

    float *pG, *pCenv, *pHidden, *pTable, *pX2, *pAgg;
    __half2* pT;
    __nv_bfloat16 *pW1h, *pW1l, *pW2h, *pW2l, *pL1h, *pL1l, *pL2h, *pL2l, *pLh, *pLl;
    cudaGetSymbolAddress((void**)&pG, g_G);
    cudaGetSymbolAddress((void**)&pCenv, g_Cenv);
    cudaGetSymbolAddress((void**)&pHidden, g_hidden);
    cudaGetSymbolAddress((void**)&pTable, g_table);
    cudaGetSymbolAddress((void**)&pX2, g_x2);
    cudaGetSymbolAddress((void**)&pAgg, g_agg);
    cudaGetSymbolAddress((void**)&pT, g_tph);
    cudaGetSymbolAddress((void**)&pW1h, g_w1T_hi); cudaGetSymbolAddress((void**)&pW1l, g_w1T_lo);
    cudaGetSymbolAddress((void**)&pW2h, g_w2T_hi); cudaGetSymbolAddress((void**)&pW2l, g_w2T_lo);
    cudaGetSymbolAddress((void**)&pL1h, g_l1T_hi); cudaGetSymbolAddress((void**)&pL1l, g_l1T_lo);
    cudaGetSymbolAddress((void**)&pL2h, g_l2T_hi); cudaGetSymbolAddress((void**)&pL2l, g_l2T_lo);
    cudaGetSymbolAddress((void**)&pLh,  g_lT_hi);  cudaGetSymbolAddress((void**)&pLl,  g_lT_lo);

    cudaFuncSetAttribute(gemm_k, cudaFuncAttributeMaxDynamicSharedMemorySize, SMEM_G);
    cudaFuncSetAttribute(linagg_k, cudaFuncAttributeMaxDynamicSharedMemorySize, SMEM_G);

    // ---- setup (coarse-grain + gaussians) ----
    setup_k<<<MCL + (TROWS * ECH + 255) / 256, 256>>>(pos, attr, sg, h);

    // ---- all weight transposes + splits (one launch) ----
    tsplit_k<<<dim3(8, 8, 5 * LINT), 256>>>(mlp_w1, mlp_w2, lin1_w, lin2_w, lin_w);

    // ---- table build, batched over all 6 layers ----
    gemm_k<<<dim3(FIL / 64, TROWS / 64, LINT), 256, SMEM_G>>>(
        pG, pW1h, pW1l, mlp_b1, nullptr, nullptr, pHidden,
        FIL, ECH, OP_BIAS | OP_SSP,
        0, (size_t)FIL * ECH, FIL, (size_t)TROWS * FIL);
    gemm_k<<<dim3(FIL / 64, TROWS / 64, LINT), 256, SMEM_G>>>(
        pHidden, pW2h, pW2l, mlp_b2, pCenv, nullptr, pTable,
        FIL, FIL, OP_BIAS | OP_ROWS,
        (size_t)TROWS * FIL, (size_t)FIL * FIL, FIL, (size_t)TROWS * FIL);
    pack_k<<<(LINT * TROWS * FIL + 255) / 256, 256>>>();

    // ---- interaction layers (3 launches each) ----
    for (int l = 0; l < LINT; l++) {
        linagg_k<<<dim3(FIL / 64, BG), 256, SMEM_G>>>(
            h, pL1h + (size_t)l * HID * FIL, pL1l + (size_t)l * HID * FIL,
            pT + (size_t)l * TROWS * FIL, pAgg);
        gemm_k<<<dim3(HID / 64, MCL / 64, 1), 256, SMEM_G>>>(
            pAgg, pL2h + (size_t)l * FIL * HID, pL2l + (size_t)l * FIL * HID,
            lin2_b + (size_t)l * HID, nullptr, nullptr, pX2, HID, FIL,
            OP_BIAS | OP_SSP, 0, 0, 0, 0);
        gemm_k<<<dim3(HID / 64, MCL / 64, 1), 256, SMEM_G>>>(
            pX2, pLh + (size_t)l * HID * HID, pLl + (size_t)l * HID * HID,
            lin_b + (size_t)l * HID, nullptr, h, h, HID, HID,
            OP_BIAS | OP_RES, 0, 0, 0, 0);
    }
}